// round 6
// baseline (speedup 1.0000x reference)
#include <cuda_runtime.h>

#define FRAME   160
#define ORDER   16
#define EPS     1e-8f
#define FPW     4                 // frames per warp
#define WARPS   4
#define THREADS (WARPS * 32)      // 128
#define FPB     (WARPS * FPW)     // 16 frames per block
#define FSTRIDE 198               // floats per frame region: 16 pad | 160 | 16 pad | 6 slack
#define PSTRIDE 99                // float2 pairs per frame region (odd -> conflict-free LDS.64)

typedef unsigned long long u64;

__device__ __forceinline__ u64 pack2(float lo, float hi) {
    u64 r; asm("mov.b64 %0, {%1, %2};" : "=l"(r) : "f"(lo), "f"(hi));
    return r;
}
__device__ __forceinline__ u64 fma2(u64 a, u64 b, u64 c) {
    u64 d; asm("fma.rn.f32x2 %0, %1, %2, %3;" : "=l"(d) : "l"(a), "l"(b), "l"(c));
    return d;
}
__device__ __forceinline__ u64 mul2(u64 a, u64 b) {
    u64 d; asm("mul.rn.f32x2 %0, %1, %2;" : "=l"(d) : "l"(a), "l"(b));
    return d;
}
__device__ __forceinline__ float lo2(u64 v) {
    float a, b; asm("mov.b64 {%0, %1}, %2;" : "=f"(a), "=f"(b) : "l"(v)); return a;
}
__device__ __forceinline__ float hi2(u64 v) {
    float a, b; asm("mov.b64 {%0, %1}, %2;" : "=f"(a), "=f"(b) : "l"(v)); return b;
}

#define BAR_SYNC(id)   asm volatile("bar.sync %0, %1;"   :: "r"(id), "r"(THREADS) : "memory")
#define BAR_ARRIVE(id) asm volatile("bar.arrive %0, %1;" :: "r"(id), "r"(THREADS) : "memory")

__global__ __launch_bounds__(THREADS, 7)
void lpc_residual_kernel(const float* __restrict__ x,
                         float* __restrict__ out,
                         int nframes)
{
    __shared__ __align__(16) float sx[WARPS * FPW * FSTRIDE];   // 12672 B
    __shared__ float rH[2][32][17];     // two 4-lane autocorr partials per frame
    __shared__ float aS[32][17];        // LPC coeffs per frame

    const int lane   = threadIdx.x & 31;
    const int wid    = threadIdx.x >> 5;
    const int frame0 = blockIdx.x * FPB + wid * FPW;            // this warp's first frame

    float* sw  = sx + wid * FPW * FSTRIDE;
    u64*   swp = (u64*)sw;

    // ---- zero pads: per frame, floats [0,16) and [176,192) => pairs [0,8) and [88,96) ----
    {
        int f = lane >> 3, c = lane & 7;
        swp[f * PSTRIDE + c]      = 0ull;
        swp[f * PSTRIDE + 88 + c] = 0ull;
    }

    // ---- stage input: 10x LDG.64 + 10x STS.64 per lane, coalesced & conflict-free ----
    {
        const float2* gx2 = (const float2*)(x + (long long)frame0 * FRAME);
        #pragma unroll
        for (int q = 0; q < 10; q++) {
            int idx = q * 32 + lane;               // float2 index within warp's 320
            int f;
            if (q == 2)      f = (lane < 16) ? 0 : 1;   // frame boundary crossings
            else if (q == 7) f = (lane < 16) ? 2 : 3;
            else             f = (q * 32) / 80;         // compile-time constant
            if (frame0 + f < nframes) {
                float2 v = gx2[idx];
                // shared pair index: f*99 + 8 + (idx - 80f) = idx + 8 + 19f
                swp[idx + 8 + 19 * f] = pack2(v.x, v.y);
            }
        }
    }
    __syncwarp();   // warp only reads its own staged frames below

    const int fl = lane >> 3;               // frame within warp (0..3)
    const int p  = lane & 7;                // sub-lane within frame (0..7)
    const int myFrame = wid * FPW + fl;     // frame index within block
    // pair index of float w[0] = x[20p] of this frame (float idx fl*198 + 16 + 20p)
    const int ubase = fl * PSTRIDE + 8 + 10 * p;
    const float2* swp2 = (const float2*)swp;

    // ---- load autocorr window w[0..35] as 18 aligned pairs ----
    float2 W[18];
    u64    WP[18];
    #pragma unroll
    for (int j = 0; j < 18; j++) {
        W[j]  = swp2[ubase + j];
        WP[j] = pack2(W[j].x, W[j].y);      // aligned pair: coalesces to same phys regs
    }

    // ---- autocorrelation: even lags packed (f32x2), odd lags scalar ----
    #pragma unroll
    for (int c = 0; c <= 8; c++) {          // k = 2c
        u64 acc = mul2(WP[0], WP[c]);
        #pragma unroll
        for (int j = 1; j < 10; j++)
            acc = fma2(WP[j], WP[j + c], acc);
        float s = lo2(acc) + hi2(acc);
        s += __shfl_xor_sync(0xFFFFFFFFu, s, 1);
        s += __shfl_xor_sync(0xFFFFFFFFu, s, 2);
        if ((p & 3) == 0) rH[p >> 2][myFrame][2 * c] = s;
    }
    #pragma unroll
    for (int c = 0; c < 8; c++) {           // k = 2c+1
        const int k = 2 * c + 1;
        float s = 0.0f;
        #pragma unroll
        for (int m = 0; m < 20; m++) {
            float wm = (m & 1) ? W[m >> 1].y : W[m >> 1].x;
            int   mk = m + k;
            float wk = (mk & 1) ? W[mk >> 1].y : W[mk >> 1].x;
            s = fmaf(wm, wk, s);
        }
        s += __shfl_xor_sync(0xFFFFFFFFu, s, 1);
        s += __shfl_xor_sync(0xFFFFFFFFu, s, 2);
        if ((p & 3) == 0) rH[p >> 2][myFrame][k] = s;
    }

    if (wid == 0) {
        // ---- consumer: wait for all partials, run Levinson (one frame per lane) ----
        BAR_SYNC(1);

        float rr[ORDER + 1];
        #pragma unroll
        for (int k = 0; k <= ORDER; k++)
            rr[k] = rH[0][lane][k] + rH[1][lane][k];

        float a[ORDER + 1];
        a[0] = 1.0f;
        float e = (rr[0] != 0.0f) ? rr[0] : EPS;
        #pragma unroll
        for (int i = 1; i <= ORDER; i++) {
            float s0 = 0.f, s1 = 0.f, s2 = 0.f, s3 = 0.f;
            #pragma unroll
            for (int j = 1; j < i; j++) {
                switch ((j - 1) & 3) {
                    case 0: s0 = fmaf(a[j], rr[i - j], s0); break;
                    case 1: s1 = fmaf(a[j], rr[i - j], s1); break;
                    case 2: s2 = fmaf(a[j], rr[i - j], s2); break;
                    default: s3 = fmaf(a[j], rr[i - j], s3); break;
                }
            }
            float acc = rr[i] - ((s0 + s1) + (s2 + s3));
            float kk = __fdividef(acc, e);
            float tn[ORDER + 1];
            #pragma unroll
            for (int j = 1; j < i; j++)
                tn[j] = fmaf(-kk, a[i - j], a[j]);
            #pragma unroll
            for (int j = 1; j < i; j++)
                a[j] = tn[j];
            a[i] = kk;
            e = fmaxf(fmaf(-kk, acc, e), EPS);   // e*(1-k^2) = e - k*acc
        }
        #pragma unroll
        for (int k = 1; k <= ORDER; k++) aS[lane][k] = a[k];

        BAR_ARRIVE(2);
        __syncwarp();       // make warp-0's own aS stores visible to its other lanes
    } else {
        BAR_ARRIVE(1);      // partials published; don't wait for Levinson to start
    }

    // ---- FIR data window: PP[j] = (v[2j], v[2j+1]), v = w[-16..19] ----
    // PP[0..7]  = history pairs (prefetched under Levinson for warps 1-3)
    // PP[8..17] = WP[0..9] (already in registers)
    u64 PP[18];
    #pragma unroll
    for (int j = 0; j < 8; j++) {
        float2 t = swp2[ubase - 8 + j];
        PP[j] = pack2(t.x, t.y);
    }
    #pragma unroll
    for (int j = 0; j < 10; j++) PP[8 + j] = WP[j];

    if (wid != 0) BAR_SYNC(2);   // wait for coefficients

    // ---- packed coefficients: aPe[c]=(a[2c],a[2c]) c=1..8, aPo[c]=(a[2c+1],a[2c+1]) c=0..7 ----
    u64 aPe[9], aPo[8];
    #pragma unroll
    for (int c = 1; c <= 8; c++) {
        float ac = aS[myFrame][2 * c];
        aPe[c] = pack2(ac, ac);
    }
    #pragma unroll
    for (int c = 0; c < 8; c++) {
        float ac = aS[myFrame][2 * c + 1];
        aPo[c] = pack2(ac, ac);
    }

    // ---- FIR (E/O packed):
    //   E[t] = PP[8+t] + sum_{c=1..8} aPe[c]*PP[8+t-c]      (a0 + even taps, outputs 2t,2t+1)
    //   O[t] = sum_{c=0..7} aPo[c]*PP[7+t-c]                 (odd taps of outputs 2t-1, 2t)
    //   y[2t] = E[t].lo + O[t].hi ;  y[2t+1] = E[t].hi + O[t+1].lo
    const bool wr = (frame0 + fl) < nframes;
    float4* go4 = (float4*)(out + (long long)(frame0 + fl) * FRAME + 20 * p);

    u64 Oprev;
    {
        u64 o = mul2(aPo[0], PP[7]);
        #pragma unroll
        for (int c = 1; c < 8; c++) o = fma2(aPo[c], PP[7 - c], o);
        Oprev = o;
    }

    float res[4];
    #pragma unroll
    for (int t = 0; t < 10; t++) {
        u64 e = fma2(aPe[1], PP[7 + t], PP[8 + t]);     // a0 term folded into fma
        #pragma unroll
        for (int c = 2; c <= 8; c++)
            e = fma2(aPe[c], PP[8 + t - c], e);

        u64 o = mul2(aPo[0], PP[8 + t]);                // O[t+1]
        #pragma unroll
        for (int c = 1; c < 8; c++)
            o = fma2(aPo[c], PP[8 + t - c], o);

        res[(2 * t) & 3]     = lo2(e) + hi2(Oprev);     // y[2t]
        res[(2 * t + 1) & 3] = hi2(e) + lo2(o);         // y[2t+1]
        Oprev = o;

        if ((t & 1) && wr)                              // every 2 t's = 4 outputs
            go4[t >> 1] = make_float4(res[0], res[1], res[2], res[3]);
    }
}

extern "C" void kernel_launch(void* const* d_in, const int* in_sizes, int n_in,
                              void* d_out, int out_size)
{
    const float* x = (const float*)d_in[0];
    float* out = (float*)d_out;

    long long total = in_sizes[0];
    int nframes = (int)(total / FRAME);                 // 128000 for the given shape
    int blocks  = (nframes + FPB - 1) / FPB;            // 8000

    lpc_residual_kernel<<<blocks, THREADS>>>(x, out, nframes);
}

// round 7
// speedup vs baseline: 1.0902x; 1.0902x over previous
#include <cuda_runtime.h>

#define FRAME   160
#define ORDER   16
#define EPS     1e-8f
#define FPW     4                 // frames per warp
#define WARPS   4
#define THREADS (WARPS * 32)      // 128
#define FPB     (WARPS * FPW)     // 16 frames per block
#define FSTRIDE 198               // floats per frame region: 16 pad | 160 | 16 pad | 6 slack
#define PSTRIDE 99                // float2 pairs per frame region (odd -> conflict-free LDS.64)

typedef unsigned long long u64;

__device__ __forceinline__ u64 pack2(float lo, float hi) {
    u64 r; asm("mov.b64 %0, {%1, %2};" : "=l"(r) : "f"(lo), "f"(hi));
    return r;
}
#define BAR_SYNC(id)   asm volatile("bar.sync %0, %1;"   :: "r"(id), "r"(THREADS) : "memory")
#define BAR_ARRIVE(id) asm volatile("bar.arrive %0, %1;" :: "r"(id), "r"(THREADS) : "memory")

__global__ __launch_bounds__(THREADS, 7)
void lpc_residual_kernel(const float* __restrict__ x,
                         float* __restrict__ out,
                         int nframes)
{
    __shared__ __align__(16) float sx[WARPS * FPW * FSTRIDE];   // 12672 B
    __shared__ float rS[32][17];        // full autocorr per frame (single partial store)
    __shared__ float aS[32][17];        // LPC coeffs per frame

    const int lane   = threadIdx.x & 31;
    const int wid    = threadIdx.x >> 5;
    const int frame0 = blockIdx.x * FPB + wid * FPW;            // this warp's first frame

    float* sw  = sx + wid * FPW * FSTRIDE;
    u64*   swp = (u64*)sw;

    // ---- zero pads: per frame, floats [0,16) and [176,192) => pairs [0,8) and [88,96) ----
    {
        int f = lane >> 3, c = lane & 7;
        swp[f * PSTRIDE + c]      = 0ull;
        swp[f * PSTRIDE + 88 + c] = 0ull;
    }

    // ---- stage input: 10x LDG.64 + 10x STS.64 per lane, coalesced & conflict-free ----
    {
        const float2* gx2 = (const float2*)(x + (long long)frame0 * FRAME);
        #pragma unroll
        for (int q = 0; q < 10; q++) {
            int idx = q * 32 + lane;               // float2 index within warp's 320
            int f;
            if (q == 2)      f = (lane < 16) ? 0 : 1;   // frame boundary crossings
            else if (q == 7) f = (lane < 16) ? 2 : 3;
            else             f = (q * 32) / 80;         // compile-time constant
            if (frame0 + f < nframes) {
                float2 v = gx2[idx];
                // shared pair index: f*99 + 8 + (idx - 80f) = idx + 8 + 19f
                swp[idx + 8 + 19 * f] = pack2(v.x, v.y);
            }
        }
    }
    __syncwarp();   // warp only reads its own staged frames below

    const int fl = lane >> 3;               // frame within warp (0..3)
    const int p  = lane & 7;                // sub-lane within frame (0..7)
    const int myFrame = wid * FPW + fl;     // frame index within block
    // pair index of float w[0] = x[20p] of this frame (float idx fl*198 + 16 + 20p)
    const int ubase = fl * PSTRIDE + 8 + 10 * p;
    const float2* swp2 = (const float2*)swp;

    // ---- autocorr window w[0..35] via 18 LDS.64; w[0..19] stays live for the FIR ----
    float w[36];
    #pragma unroll
    for (int j = 0; j < 18; j++) {
        float2 t = swp2[ubase + j];
        w[2 * j] = t.x; w[2 * j + 1] = t.y;
    }

    // ---- autocorrelation: r[k] = sum_m w[m] w[m+k]; full 3-stage butterfly ----
    #pragma unroll
    for (int k = 0; k <= ORDER; k++) {
        float acc = 0.0f;
        #pragma unroll
        for (int m = 0; m < 20; m++)
            acc = fmaf(w[m], w[m + k], acc);
        acc += __shfl_xor_sync(0xFFFFFFFFu, acc, 1);
        acc += __shfl_xor_sync(0xFFFFFFFFu, acc, 2);
        acc += __shfl_xor_sync(0xFFFFFFFFu, acc, 4);
        if (p == 0) rS[myFrame][k] = acc;       // complete r -> Levinson warp does no adds
    }

    if (wid == 0) {
        // ---- consumer: wait for all partials, run Levinson (one frame per lane) ----
        BAR_SYNC(1);

        float rr[ORDER + 1];
        #pragma unroll
        for (int k = 0; k <= ORDER; k++)
            rr[k] = rS[lane][k];                // stride-17 (odd) -> conflict-free

        float a[ORDER + 1];
        a[0] = 1.0f;
        float e = (rr[0] != 0.0f) ? rr[0] : EPS;
        #pragma unroll
        for (int i = 1; i <= ORDER; i++) {
            float s0 = 0.f, s1 = 0.f, s2 = 0.f, s3 = 0.f;
            #pragma unroll
            for (int j = 1; j < i; j++) {
                switch ((j - 1) & 3) {
                    case 0: s0 = fmaf(a[j], rr[i - j], s0); break;
                    case 1: s1 = fmaf(a[j], rr[i - j], s1); break;
                    case 2: s2 = fmaf(a[j], rr[i - j], s2); break;
                    default: s3 = fmaf(a[j], rr[i - j], s3); break;
                }
            }
            float acc = rr[i] - ((s0 + s1) + (s2 + s3));
            float kk = __fdividef(acc, e);
            float tn[ORDER + 1];
            #pragma unroll
            for (int j = 1; j < i; j++)
                tn[j] = fmaf(-kk, a[i - j], a[j]);
            #pragma unroll
            for (int j = 1; j < i; j++)
                a[j] = tn[j];
            a[i] = kk;
            e = fmaxf(fmaf(-kk, acc, e), EPS);   // e*(1-k^2) = e - k*acc
        }
        #pragma unroll
        for (int k = 1; k <= ORDER; k++) aS[lane][k] = a[k];

        BAR_ARRIVE(2);
        __syncwarp();       // make warp-0's own aS stores visible to its other lanes
    } else {
        BAR_ARRIVE(1);      // partials published; don't wait for Levinson to start
    }

    // ---- history w[-16..-1] via 8 LDS.64 (prefetched under Levinson for warps 1-3);
    //      main window w[0..19] is already in registers from the autocorrelation ----
    float v[16];
    #pragma unroll
    for (int j = 0; j < 8; j++) {
        float2 t = swp2[ubase - 8 + j];
        v[2 * j] = t.x; v[2 * j + 1] = t.y;
    }

    if (wid != 0) BAR_SYNC(2);   // wait for coefficients

    // ---- broadcast coeffs (8-lane broadcast per frame, conflict-free) ----
    float a[ORDER + 1];
    #pragma unroll
    for (int k = 1; k <= ORDER; k++) a[k] = aS[myFrame][k];

    // ---- FIR: res[n] = w[n] + sum_{k=1}^{16} a[k] * w[n-k]; store as float4 groups ----
    const bool wr = (frame0 + fl) < nframes;
    float4* go4 = (float4*)(out + (long long)(frame0 + fl) * FRAME + 20 * p);

    #pragma unroll
    for (int g = 0; g < 5; g++) {
        float res[4];
        #pragma unroll
        for (int h = 0; h < 4; h++) {
            int m = 4 * g + h;
            float s = w[m];                    // a[0] = 1 term
            #pragma unroll
            for (int k = 1; k <= ORDER; k++) {
                int i = m - k;
                s = fmaf(a[k], (i >= 0) ? w[i] : v[16 + i], s);
            }
            res[h] = s;
        }
        if (wr) go4[g] = make_float4(res[0], res[1], res[2], res[3]);
    }
}

extern "C" void kernel_launch(void* const* d_in, const int* in_sizes, int n_in,
                              void* d_out, int out_size)
{
    const float* x = (const float*)d_in[0];
    float* out = (float*)d_out;

    long long total = in_sizes[0];
    int nframes = (int)(total / FRAME);                 // 128000 for the given shape
    int blocks  = (nframes + FPB - 1) / FPB;            // 8000

    lpc_residual_kernel<<<blocks, THREADS>>>(x, out, nframes);
}

// round 8
// speedup vs baseline: 1.1472x; 1.0522x over previous
#include <cuda_runtime.h>

#define FRAME   160
#define ORDER   16
#define EPS     1e-8f
#define FPW     4                 // frames per warp
#define WARPS   4
#define THREADS (WARPS * 32)      // 128
#define FPB     (WARPS * FPW)     // 16 frames per block
#define FSTRIDE 198               // floats per frame region: 16 pad | 160 | 16 pad | 6 slack
#define PSTRIDE 99                // float2 pairs per frame region (odd -> conflict-free LDS.64)

typedef unsigned long long u64;

__device__ __forceinline__ u64 pack2(float lo, float hi) {
    u64 r; asm("mov.b64 %0, {%1, %2};" : "=l"(r) : "f"(lo), "f"(hi));
    return r;
}
#define BAR_SYNC(id)   asm volatile("bar.sync %0, %1;"   :: "r"(id), "r"(THREADS) : "memory")
#define BAR_ARRIVE(id) asm volatile("bar.arrive %0, %1;" :: "r"(id), "r"(THREADS) : "memory")

__global__ __launch_bounds__(THREADS, 8)
void lpc_residual_kernel(const float* __restrict__ x,
                         float* __restrict__ out,
                         int nframes)
{
    __shared__ __align__(16) float sx[WARPS * FPW * FSTRIDE];   // 12672 B
    __shared__ float rS[32][17];        // full autocorr per frame
    __shared__ float aS[32][17];        // LPC coeffs per frame

    const int lane   = threadIdx.x & 31;
    const int wid    = threadIdx.x >> 5;
    const int frame0 = blockIdx.x * FPB + wid * FPW;            // this warp's first frame

    float* sw  = sx + wid * FPW * FSTRIDE;
    u64*   swp = (u64*)sw;

    // ---- zero pads: per frame, floats [0,16) and [176,192) => pairs [0,8) and [88,96) ----
    {
        int f = lane >> 3, c = lane & 7;
        swp[f * PSTRIDE + c]      = 0ull;
        swp[f * PSTRIDE + 88 + c] = 0ull;
    }

    // ---- stage input: 10x LDG.64 + 10x STS.64 per lane, coalesced & conflict-free ----
    {
        const float2* gx2 = (const float2*)(x + (long long)frame0 * FRAME);
        #pragma unroll
        for (int q = 0; q < 10; q++) {
            int idx = q * 32 + lane;               // float2 index within warp's 320
            int f;
            if (q == 2)      f = (lane < 16) ? 0 : 1;   // frame boundary crossings
            else if (q == 7) f = (lane < 16) ? 2 : 3;
            else             f = (q * 32) / 80;         // compile-time constant
            if (frame0 + f < nframes) {
                float2 v = gx2[idx];
                // shared pair index: f*99 + 8 + (idx - 80f) = idx + 8 + 19f
                swp[idx + 8 + 19 * f] = pack2(v.x, v.y);
            }
        }
    }
    __syncwarp();   // warp only reads its own staged frames below

    const int fl = lane >> 3;               // frame within warp (0..3)
    const int p  = lane & 7;                // sub-lane within frame (0..7)
    const int myFrame = wid * FPW + fl;     // frame index within block
    // pair index of float w[0] = x[20p] of this frame (float idx fl*198 + 16 + 20p)
    const int ubase = fl * PSTRIDE + 8 + 10 * p;
    const float2* swp2 = (const float2*)swp;

    // ---- autocorr window w[0..35] via 18 LDS.64; w[0..19] stays live for the FIR ----
    float w[36];
    #pragma unroll
    for (int j = 0; j < 18; j++) {
        float2 t = swp2[ubase + j];
        w[2 * j] = t.x; w[2 * j + 1] = t.y;
    }

    // ---- autocorrelation: r[k] = sum_m w[m] w[m+k]; full 3-stage butterfly ----
    #pragma unroll
    for (int k = 0; k <= ORDER; k++) {
        float acc = 0.0f;
        #pragma unroll
        for (int m = 0; m < 20; m++)
            acc = fmaf(w[m], w[m + k], acc);
        acc += __shfl_xor_sync(0xFFFFFFFFu, acc, 1);
        acc += __shfl_xor_sync(0xFFFFFFFFu, acc, 2);
        acc += __shfl_xor_sync(0xFFFFFFFFu, acc, 4);
        if (p == 0) rS[myFrame][k] = acc;       // complete r -> Levinson warp does no adds
    }

    if (wid == 0) {
        // ---- consumer: wait for all partials, run Levinson (one frame per lane) ----
        BAR_SYNC(1);

        float rr[ORDER + 1];
        #pragma unroll
        for (int k = 0; k <= ORDER; k++)
            rr[k] = rS[lane][k];                // stride-17 (odd) -> conflict-free

        float a[ORDER + 1];
        a[0] = 1.0f;
        float e = (rr[0] != 0.0f) ? rr[0] : EPS;
        #pragma unroll
        for (int i = 1; i <= ORDER; i++) {
            float s0 = 0.f, s1 = 0.f, s2 = 0.f, s3 = 0.f;
            #pragma unroll
            for (int j = 1; j < i; j++) {
                switch ((j - 1) & 3) {
                    case 0: s0 = fmaf(a[j], rr[i - j], s0); break;
                    case 1: s1 = fmaf(a[j], rr[i - j], s1); break;
                    case 2: s2 = fmaf(a[j], rr[i - j], s2); break;
                    default: s3 = fmaf(a[j], rr[i - j], s3); break;
                }
            }
            float acc = rr[i] - ((s0 + s1) + (s2 + s3));
            float kk = __fdividef(acc, e);
            float tn[ORDER + 1];
            #pragma unroll
            for (int j = 1; j < i; j++)
                tn[j] = fmaf(-kk, a[i - j], a[j]);
            #pragma unroll
            for (int j = 1; j < i; j++)
                a[j] = tn[j];
            a[i] = kk;
            e = fmaxf(fmaf(-kk, acc, e), EPS);   // e*(1-k^2) = e - k*acc
        }
        #pragma unroll
        for (int k = 1; k <= ORDER; k++) aS[lane][k] = a[k];

        BAR_ARRIVE(2);
        __syncwarp();       // make warp-0's own aS stores visible to its other lanes
    } else {
        BAR_ARRIVE(1);      // partials published; don't wait for Levinson to start
    }

    // ---- history w[-16..-1] via 8 LDS.64 (prefetched under Levinson for warps 1-3);
    //      main window w[0..19] is already in registers from the autocorrelation ----
    float v[16];
    #pragma unroll
    for (int j = 0; j < 8; j++) {
        float2 t = swp2[ubase - 8 + j];
        v[2 * j] = t.x; v[2 * j + 1] = t.y;
    }

    if (wid != 0) BAR_SYNC(2);   // wait for coefficients

    // ---- broadcast coeffs (8-lane broadcast per frame, conflict-free) ----
    float a[ORDER + 1];
    #pragma unroll
    for (int k = 1; k <= ORDER; k++) a[k] = aS[myFrame][k];

    // ---- FIR: res[n] = w[n] + sum_{k=1}^{16} a[k] * w[n-k]; store as float4 groups ----
    const bool wr = (frame0 + fl) < nframes;
    float4* go4 = (float4*)(out + (long long)(frame0 + fl) * FRAME + 20 * p);

    #pragma unroll
    for (int g = 0; g < 5; g++) {
        float res[4];
        #pragma unroll
        for (int h = 0; h < 4; h++) {
            int m = 4 * g + h;
            float s = w[m];                    // a[0] = 1 term
            #pragma unroll
            for (int k = 1; k <= ORDER; k++) {
                int i = m - k;
                s = fmaf(a[k], (i >= 0) ? w[i] : v[16 + i], s);
            }
            res[h] = s;
        }
        if (wr) go4[g] = make_float4(res[0], res[1], res[2], res[3]);
    }
}

extern "C" void kernel_launch(void* const* d_in, const int* in_sizes, int n_in,
                              void* d_out, int out_size)
{
    const float* x = (const float*)d_in[0];
    float* out = (float*)d_out;

    long long total = in_sizes[0];
    int nframes = (int)(total / FRAME);                 // 128000 for the given shape
    int blocks  = (nframes + FPB - 1) / FPB;            // 8000

    lpc_residual_kernel<<<blocks, THREADS>>>(x, out, nframes);
}